// round 16
// baseline (speedup 1.0000x reference)
#include <cuda_runtime.h>
#include <cuda_fp16.h>
#include <cstdint>
#include <cstddef>

namespace {

constexpr int S = 1024, D = 64, BH = 128;

__device__ __half g_Khf[(size_t)BH * S * D];
__device__ __half g_Vhf[(size_t)BH * S * D];

// ---------------- helpers ----------------
__device__ __forceinline__ uint32_t smem_u32(const void* p) {
    uint32_t a;
    asm("{ .reg .u64 t; cvta.to.shared.u64 t, %1; cvt.u32.u64 %0, t; }" : "=r"(a) : "l"(p));
    return a;
}
__device__ __forceinline__ uint32_t SWZ(uint32_t b) { return b ^ ((b >> 3) & 0x70); }

__device__ __forceinline__ uint32_t packh2(float x, float y) {
    __half2 h = __floats2half2_rn(x, y);
    return *reinterpret_cast<uint32_t*>(&h);
}
__device__ __forceinline__ float2 unpackh2(uint32_t u) {
    __half2 h = *reinterpret_cast<__half2*>(&u);
    return __half22float2(h);
}

// Q: two-term fp16 split (hi + residual)
__device__ __forceinline__ void st_split4h(char* hi, char* lo, uint32_t b0, float4 v) {
    uint32_t hA = packh2(v.x, v.y), hB = packh2(v.z, v.w);
    float2 fA = unpackh2(hA), fB = unpackh2(hB);
    uint32_t lA = packh2(v.x - fA.x, v.y - fA.y);
    uint32_t lB = packh2(v.z - fB.x, v.w - fB.y);
    uint32_t o = SWZ(b0);
    *reinterpret_cast<uint2*>(hi + o) = make_uint2(hA, hB);
    *reinterpret_cast<uint2*>(lo + o) = make_uint2(lA, lB);
}

__device__ __forceinline__ void cp16(uint32_t saddr, const void* g) {
    asm volatile("cp.async.cg.shared.global [%0], [%1], 16;" :: "r"(saddr), "l"(g));
}
__device__ __forceinline__ void cp_commit() {
    asm volatile("cp.async.commit_group;" ::: "memory");
}
template <int N>
__device__ __forceinline__ void cp_wait() {
    asm volatile("cp.async.wait_group %0;" :: "n"(N) : "memory");
}

__device__ __forceinline__ void ldsm_x4(uint32_t* r, uint32_t addr) {
    asm volatile("ldmatrix.sync.aligned.m8n8.x4.shared.b16 {%0,%1,%2,%3}, [%4];"
                 : "=r"(r[0]), "=r"(r[1]), "=r"(r[2]), "=r"(r[3]) : "r"(addr));
}
__device__ __forceinline__ void ldsm_x4t(uint32_t* r, uint32_t addr) {
    asm volatile("ldmatrix.sync.aligned.m8n8.x4.trans.shared.b16 {%0,%1,%2,%3}, [%4];"
                 : "=r"(r[0]), "=r"(r[1]), "=r"(r[2]), "=r"(r[3]) : "r"(addr));
}
__device__ __forceinline__ void mma_f16(float* c, const uint32_t* a, const uint32_t* b) {
    asm volatile("mma.sync.aligned.m16n8k16.row.col.f32.f16.f16.f32 "
                 "{%0,%1,%2,%3}, {%4,%5,%6,%7}, {%8,%9}, {%0,%1,%2,%3};"
                 : "+f"(c[0]), "+f"(c[1]), "+f"(c[2]), "+f"(c[3])
                 : "r"(a[0]), "r"(a[1]), "r"(a[2]), "r"(a[3]), "r"(b[0]), "r"(b[1]));
}

// ================= K/V fp32 -> fp16 pre-convert =================
__global__ void __launch_bounds__(256)
cvt_kernel(const float4* __restrict__ K, const float4* __restrict__ V)
{
    size_t i = (size_t)blockIdx.x * 256 + threadIdx.x;   // over 2,097,152 float4
    float4 k = K[i], v = V[i];
    reinterpret_cast<uint2*>(g_Khf)[i] = make_uint2(packh2(k.x, k.y), packh2(k.z, k.w));
    reinterpret_cast<uint2*>(g_Vhf)[i] = make_uint2(packh2(v.x, v.y), packh2(v.z, v.w));
}

// smem layout (bytes): mask 16K | K0 16K | K1 16K | V0 16K | V1 16K | stage 16K
constexpr int SM_MK = 0, SM_K0 = 16384, SM_K1 = 32768, SM_V0 = 49152, SM_V1 = 65536, SM_PS = 81920;
constexpr int SMEM_BYTES = 98304;

__global__ void __launch_bounds__(256, 2)
sdpa_fused(const float* __restrict__ Q, const uint8_t* __restrict__ M,
           float* __restrict__ P, float* __restrict__ O)
{
    extern __shared__ char sm[];
    const uint32_t sb = smem_u32(sm);
    uint32_t* smMask = (uint32_t*)(sm + SM_MK);
    const int tid = threadIdx.x, wid = tid >> 5, lane = tid & 31;
    const int bh = blockIdx.y, q0 = blockIdx.x * 128;

    int pred = (tid < 128) ? (M[4 * tid + 1] != 0) : 0;
    const bool mask1B = (__syncthreads_or(pred) != 0);

    const uint8_t* M8  = M + ((size_t)bh * S + q0) * (size_t)S;
    const int*     M32 = (const int*)M + ((size_t)bh * S + q0) * (size_t)S;

    // ---- pack mask into smem bits (vcmpne4 + multiply-gather) ----
    for (int w = tid; w < 4096; w += 256) {
        int row = w >> 5, g = w & 31;
        uint32_t bits = 0;
        if (mask1B) {
            const uint8_t* p = M8 + (size_t)row * S + g * 32;
            uint4 a = *(const uint4*)p;
            uint4 b = *(const uint4*)(p + 16);
            uint32_t ww[8] = {a.x, a.y, a.z, a.w, b.x, b.y, b.z, b.w};
            #pragma unroll
            for (int j = 0; j < 8; j++) {
                uint32_t nib = ((__vcmpne4(ww[j], 0u) & 0x01010101u) * 0x01020408u) >> 24;
                bits |= nib << (j * 4);
            }
        } else {
            const int4* p = (const int4*)(M32 + (size_t)row * S + g * 32);
            #pragma unroll
            for (int j = 0; j < 8; j++) {
                int4 v = p[j];
                bits |= (uint32_t)(v.x != 0) << (j * 4);
                bits |= (uint32_t)(v.y != 0) << (j * 4 + 1);
                bits |= (uint32_t)(v.z != 0) << (j * 4 + 2);
                bits |= (uint32_t)(v.w != 0) << (j * 4 + 3);
            }
        }
        smMask[w] = bits;
    }

    // ---- Q -> split fp16 (hi into K0, lo into V0; consumed before tile loads) ----
    const float4* Qg4 = (const float4*)(Q + ((size_t)bh * S + q0) * D);
    #pragma unroll
    for (int i = 0; i < 8; i++) {
        int idx = tid + i * 256;
        int r = idx >> 4, c4 = idx & 15;
        float4 v = Qg4[idx];
        v.x *= 0.125f; v.y *= 0.125f; v.z *= 0.125f; v.w *= 0.125f;
        st_split4h(sm + SM_K0, sm + SM_V0, (uint32_t)(r * 128 + c4 * 8), v);
    }
    __syncthreads();

    uint32_t ah[4][4], al[4][4];
    {
        int j = lane >> 3, ii = lane & 7;
        int row = wid * 16 + ((j & 1) << 3) + ii;
        #pragma unroll
        for (int ks = 0; ks < 4; ks++) {
            uint32_t off = SWZ((uint32_t)(row * 128 + ((j >> 1) << 4) + ks * 32));
            ldsm_x4(ah[ks], sb + SM_K0 + off);
            ldsm_x4(al[ks], sb + SM_V0 + off);
        }
    }
    __syncthreads();   // frags hoisted; K0/V0 reusable as tile buffers

    const char* Khf = (const char*)(g_Khf + (size_t)bh * S * D);
    const char* Vhf = (const char*)(g_Vhf + (size_t)bh * S * D);

    const int r0 = wid * 16 + (lane >> 2);
    const int r1 = r0 + 8;
    const int sh2 = 2 * (lane & 3);

    const uint32_t bQrow = (uint32_t)(lane & 7);
    const uint32_t bQcol = (uint32_t)(((lane >> 3) & 1) * 16 + (lane >> 4) * 32);
    const uint32_t bVrow = (uint32_t)(((lane >> 3) & 1) * 8 + (lane & 7));
    const uint32_t bVcol = (uint32_t)((lane >> 4) * 16);

    // ---- precomputed swizzled offsets (SWZ XOR source bits are lane-const) ----
    uint32_t qkOff[2];
    {
        uint32_t xr = bQrow << 4;                     // bQrow < 8
        qkOff[0] = bQrow * 128 + ((bQcol)      ^ xr);
        qkOff[1] = bQrow * 128 + ((bQcol + 64) ^ xr);
    }
    uint32_t pvOff[4];
    {
        uint32_t xr = (bVrow & 7u) << 4;
        #pragma unroll
        for (int nt2 = 0; nt2 < 4; nt2++)
            pvOff[nt2] = bVrow * 128 + (((uint32_t)(nt2 * 32) + bVcol) ^ xr);
    }
    const uint32_t stXor = ((uint32_t)(r0 & 7)) << 4;  // r1&7 == r0&7
    const uint32_t stA = (uint32_t)(r0 * 128), stB = (uint32_t)(r1 * 128);

    // tile loader: 16 KB tile = 128 rows x 8 chunks of 16B = 1024 chunks, 4 per thread
    auto loadTile = [&](int bufOff, const char* base) {
        #pragma unroll
        for (int i = 0; i < 4; i++) {
            int idx = tid + i * 256;                 // 0..1023
            uint32_t boff = (uint32_t)((idx >> 3) * 128 + (idx & 7) * 16);
            cp16(sb + bufOff + SWZ(boff), base + boff);
        }
    };

    // ================= Pass 1: stats (fp16 hi-only scores) =================
    float rmax0 = -3.4e38f, rmax1 = -3.4e38f, rsum0 = 0.f, rsum1 = 0.f;

    loadTile(SM_K0, Khf);
    cp_commit();

    for (int c = 0; c < 8; c++) {
        if (c < 7) { loadTile((c & 1) ? SM_K0 : SM_K1, Khf + (size_t)(c + 1) * 16384); cp_commit(); cp_wait<1>(); }
        else       { cp_wait<0>(); }
        __syncthreads();
        const uint32_t kb = sb + ((c & 1) ? SM_K1 : SM_K0);

        #pragma unroll
        for (int g = 0; g < 2; g++) {
            float cf[8][4];
            #pragma unroll
            for (int n8 = 0; n8 < 8; n8++) {
                cf[n8][0] = cf[n8][1] = cf[n8][2] = cf[n8][3] = 0.f;
                int nt = g * 8 + n8;
                #pragma unroll
                for (int ks2 = 0; ks2 < 2; ks2++) {
                    uint32_t off = (uint32_t)(nt * 1024) + qkOff[ks2];
                    uint32_t bh4[4];
                    ldsm_x4(bh4, kb + off);
                    mma_f16(cf[n8], ah[2*ks2],   bh4);
                    mma_f16(cf[n8], ah[2*ks2+1], bh4 + 2);
                }
            }
            uint32_t w0a = smMask[r0 * 32 + c * 4 + g * 2];
            uint32_t w0b = smMask[r0 * 32 + c * 4 + g * 2 + 1];
            uint32_t w1a = smMask[r1 * 32 + c * 4 + g * 2];
            uint32_t w1b = smMask[r1 * 32 + c * 4 + g * 2 + 1];
            float gm0 = -3.4e38f, gm1 = -3.4e38f;
            #pragma unroll
            for (int n8 = 0; n8 < 8; n8++) {
                uint32_t m0 = ((n8 < 4 ? w0a : w0b) >> ((n8 & 3) * 8 + sh2)) & 3u;
                uint32_t m1 = ((n8 < 4 ? w1a : w1b) >> ((n8 & 3) * 8 + sh2)) & 3u;
                cf[n8][0] = (m0 & 1u) ? -1e9f : cf[n8][0];
                cf[n8][1] = (m0 & 2u) ? -1e9f : cf[n8][1];
                cf[n8][2] = (m1 & 1u) ? -1e9f : cf[n8][2];
                cf[n8][3] = (m1 & 2u) ? -1e9f : cf[n8][3];
                gm0 = fmaxf(gm0, fmaxf(cf[n8][0], cf[n8][1]));
                gm1 = fmaxf(gm1, fmaxf(cf[n8][2], cf[n8][3]));
            }
            float nm0 = fmaxf(rmax0, gm0), nm1 = fmaxf(rmax1, gm1);
            float s0 = 0.f, s1 = 0.f;
            #pragma unroll
            for (int n8 = 0; n8 < 8; n8++) {
                s0 += __expf(cf[n8][0] - nm0) + __expf(cf[n8][1] - nm0);
                s1 += __expf(cf[n8][2] - nm1) + __expf(cf[n8][3] - nm1);
            }
            rsum0 = rsum0 * __expf(rmax0 - nm0) + s0; rmax0 = nm0;
            rsum1 = rsum1 * __expf(rmax1 - nm1) + s1; rmax1 = nm1;
        }
        __syncthreads();
    }

    // quad reduce (lanes sharing a row)
    #pragma unroll
    for (int o = 1; o <= 2; o <<= 1) {
        float om = __shfl_xor_sync(0xffffffffu, rmax0, o);
        float os = __shfl_xor_sync(0xffffffffu, rsum0, o);
        float nm = fmaxf(rmax0, om);
        rsum0 = rsum0 * __expf(rmax0 - nm) + os * __expf(om - nm); rmax0 = nm;
        om = __shfl_xor_sync(0xffffffffu, rmax1, o);
        os = __shfl_xor_sync(0xffffffffu, rsum1, o);
        nm = fmaxf(rmax1, om);
        rsum1 = rsum1 * __expf(rmax1 - nm) + os * __expf(om - nm); rmax1 = nm;
    }
    const float mx0 = rmax0, iv0 = 1.0f / rsum0;
    const float mx1 = rmax1, iv1 = 1.0f / rsum1;

    // ================= Pass 2: probs + PV =================
    float co[8][4];
    #pragma unroll
    for (int n = 0; n < 8; n++) co[n][0] = co[n][1] = co[n][2] = co[n][3] = 0.f;

    float* Ag = P + ((size_t)bh * S + q0) * (size_t)S;

    loadTile(SM_K0, Khf);
    loadTile(SM_V0, Vhf);
    cp_commit();

    for (int t = 0; t < 8; t++) {
        if (t < 7) {
            loadTile((t & 1) ? SM_K0 : SM_K1, Khf + (size_t)(t + 1) * 16384);
            loadTile((t & 1) ? SM_V0 : SM_V1, Vhf + (size_t)(t + 1) * 16384);
            cp_commit();
            cp_wait<1>();
        } else {
            cp_wait<0>();
        }
        __syncthreads();
        const uint32_t kb = sb + ((t & 1) ? SM_K1 : SM_K0);
        const uint32_t vb = sb + ((t & 1) ? SM_V1 : SM_V0);

        #pragma unroll
        for (int g2 = 0; g2 < 4; g2++) {          // 32-key batches
            float cf[4][4];
            #pragma unroll
            for (int n8 = 0; n8 < 4; n8++) {
                cf[n8][0] = cf[n8][1] = cf[n8][2] = cf[n8][3] = 0.f;
                int nt = g2 * 4 + n8;
                #pragma unroll
                for (int ks2 = 0; ks2 < 2; ks2++) {
                    uint32_t off = (uint32_t)(nt * 1024) + qkOff[ks2];
                    uint32_t bh4[4];
                    ldsm_x4(bh4, kb + off);
                    mma_f16(cf[n8], ah[2*ks2],   bh4);
                    mma_f16(cf[n8], al[2*ks2],   bh4);
                    mma_f16(cf[n8], ah[2*ks2+1], bh4 + 2);
                    mma_f16(cf[n8], al[2*ks2+1], bh4 + 2);
                }
            }
            uint32_t w0 = smMask[r0 * 32 + t * 4 + g2];
            uint32_t w1 = smMask[r1 * 32 + t * 4 + g2];
            uint32_t ph[2][4], pl[2][4];
            #pragma unroll
            for (int n8 = 0; n8 < 4; n8++) {
                uint32_t stC = ((uint32_t)(n8 * 32 + sh2 * 4)) ^ stXor;
                uint32_t m0 = (w0 >> (n8 * 8 + sh2)) & 3u;
                uint32_t m1 = (w1 >> (n8 * 8 + sh2)) & 3u;
                float p0 = (m0 & 1u) ? 0.f : __expf(cf[n8][0] - mx0) * iv0;
                float p1 = (m0 & 2u) ? 0.f : __expf(cf[n8][1] - mx0) * iv0;
                float p2 = (m1 & 1u) ? 0.f : __expf(cf[n8][2] - mx1) * iv1;
                float p3 = (m1 & 2u) ? 0.f : __expf(cf[n8][3] - mx1) * iv1;
                *(float2*)(sm + SM_PS + (stA + stC)) = make_float2(p0, p1);
                *(float2*)(sm + SM_PS + (stB + stC)) = make_float2(p2, p3);
                uint32_t h01 = packh2(p0, p1), h23 = packh2(p2, p3);
                float2 f01 = unpackh2(h01), f23 = unpackh2(h23);
                uint32_t l01 = packh2(p0 - f01.x, p1 - f01.y);
                uint32_t l23 = packh2(p2 - f23.x, p3 - f23.y);
                int ks2 = n8 >> 1, hi2 = (n8 & 1) << 1;
                ph[ks2][hi2] = h01; ph[ks2][hi2 + 1] = h23;
                pl[ks2][hi2] = l01; pl[ks2][hi2 + 1] = l23;
            }
            __syncthreads();   // staging complete across warps
            #pragma unroll
            for (int i = 0; i < 4; i++) {
                int idx = tid + i * 256;            // 0..1023
                int row = idx >> 3, c4 = idx & 7;
                float4 pv = *(const float4*)(sm + SM_PS + SWZ((uint32_t)(row * 128 + c4 * 16)));
                *(float4*)(Ag + (size_t)row * S + t * 128 + g2 * 32 + c4 * 4) = pv;
            }
            // PV accumulate (V single fp16, P split in registers)
            #pragma unroll
            for (int ks2 = 0; ks2 < 2; ks2++) {
                #pragma unroll
                for (int nt2 = 0; nt2 < 4; nt2++) {
                    uint32_t off = (uint32_t)((g2 * 32 + ks2 * 16) * 128) + pvOff[nt2];
                    uint32_t bh4[4];
                    ldsm_x4t(bh4, vb + off);
                    mma_f16(co[2*nt2],   ph[ks2], bh4);
                    mma_f16(co[2*nt2],   pl[ks2], bh4);
                    mma_f16(co[2*nt2+1], ph[ks2], bh4 + 2);
                    mma_f16(co[2*nt2+1], pl[ks2], bh4 + 2);
                }
            }
            __syncthreads();   // staging readback done before next batch overwrites
        }
    }

    // ---- write context ----
    float* Og = O + ((size_t)bh * S + q0) * D;
    #pragma unroll
    for (int nt = 0; nt < 8; nt++) {
        int col = nt * 8 + sh2;
        *(float2*)(Og + (size_t)r0 * D + col) = make_float2(co[nt][0], co[nt][1]);
        *(float2*)(Og + (size_t)r1 * D + col) = make_float2(co[nt][2], co[nt][3]);
    }
}

} // namespace

extern "C" void kernel_launch(void* const* d_in, const int* in_sizes, int n_in,
                              void* d_out, int out_size) {
    const float*   Q = (const float*)d_in[0];
    const float*   K = (const float*)d_in[1];
    const float*   V = (const float*)d_in[2];
    const uint8_t* M = (const uint8_t*)d_in[3];

    const long long NCTX = 8LL * 16 * 1024 * 64;
    const long long NATT = 8LL * 16 * 1024 * 1024;

    float* ctx  = nullptr;
    float* attn = nullptr;
    if ((long long)out_size >= NCTX + NATT) {
        ctx  = (float*)d_out;
        attn = (float*)d_out + NCTX;
    } else if ((long long)out_size == NATT) {
        attn = (float*)d_out;
    } else {
        ctx = (float*)d_out;
    }
    if (!attn || !ctx) return;

    cudaFuncSetAttribute((const void*)sdpa_fused,
                         cudaFuncAttributeMaxDynamicSharedMemorySize, SMEM_BYTES);

    cvt_kernel<<<8192, 256>>>((const float4*)K, (const float4*)V);

    dim3 grid(8, BH);
    sdpa_fused<<<grid, 256, SMEM_BYTES>>>(Q, M, attn, ctx);
}

// round 17
// speedup vs baseline: 1.0459x; 1.0459x over previous
#include <cuda_runtime.h>
#include <cuda_fp16.h>
#include <cstdint>
#include <cstddef>

namespace {

constexpr int S = 1024, D = 64, BH = 128;

__device__ __half g_Khf[(size_t)BH * S * D];
__device__ __half g_Vhf[(size_t)BH * S * D];

// ---------------- helpers ----------------
__device__ __forceinline__ uint32_t smem_u32(const void* p) {
    uint32_t a;
    asm("{ .reg .u64 t; cvta.to.shared.u64 t, %1; cvt.u32.u64 %0, t; }" : "=r"(a) : "l"(p));
    return a;
}
__device__ __forceinline__ uint32_t SWZ(uint32_t b) { return b ^ ((b >> 3) & 0x70); }

__device__ __forceinline__ uint32_t packh2(float x, float y) {
    __half2 h = __floats2half2_rn(x, y);
    return *reinterpret_cast<uint32_t*>(&h);
}
__device__ __forceinline__ float2 unpackh2(uint32_t u) {
    __half2 h = *reinterpret_cast<__half2*>(&u);
    return __half22float2(h);
}

// Q: two-term fp16 split (hi + residual)
__device__ __forceinline__ void st_split4h(char* hi, char* lo, uint32_t b0, float4 v) {
    uint32_t hA = packh2(v.x, v.y), hB = packh2(v.z, v.w);
    float2 fA = unpackh2(hA), fB = unpackh2(hB);
    uint32_t lA = packh2(v.x - fA.x, v.y - fA.y);
    uint32_t lB = packh2(v.z - fB.x, v.w - fB.y);
    uint32_t o = SWZ(b0);
    *reinterpret_cast<uint2*>(hi + o) = make_uint2(hA, hB);
    *reinterpret_cast<uint2*>(lo + o) = make_uint2(lA, lB);
}

__device__ __forceinline__ void cp16(uint32_t saddr, const void* g) {
    asm volatile("cp.async.cg.shared.global [%0], [%1], 16;" :: "r"(saddr), "l"(g));
}
__device__ __forceinline__ void cp_commit() {
    asm volatile("cp.async.commit_group;" ::: "memory");
}
template <int N>
__device__ __forceinline__ void cp_wait() {
    asm volatile("cp.async.wait_group %0;" :: "n"(N) : "memory");
}

__device__ __forceinline__ void ldsm_x4(uint32_t* r, uint32_t addr) {
    asm volatile("ldmatrix.sync.aligned.m8n8.x4.shared.b16 {%0,%1,%2,%3}, [%4];"
                 : "=r"(r[0]), "=r"(r[1]), "=r"(r[2]), "=r"(r[3]) : "r"(addr));
}
__device__ __forceinline__ void ldsm_x4t(uint32_t* r, uint32_t addr) {
    asm volatile("ldmatrix.sync.aligned.m8n8.x4.trans.shared.b16 {%0,%1,%2,%3}, [%4];"
                 : "=r"(r[0]), "=r"(r[1]), "=r"(r[2]), "=r"(r[3]) : "r"(addr));
}
__device__ __forceinline__ void mma_f16(float* c, const uint32_t* a, const uint32_t* b) {
    asm volatile("mma.sync.aligned.m16n8k16.row.col.f32.f16.f16.f32 "
                 "{%0,%1,%2,%3}, {%4,%5,%6,%7}, {%8,%9}, {%0,%1,%2,%3};"
                 : "+f"(c[0]), "+f"(c[1]), "+f"(c[2]), "+f"(c[3])
                 : "r"(a[0]), "r"(a[1]), "r"(a[2]), "r"(a[3]), "r"(b[0]), "r"(b[1]));
}

// ================= K/V fp32 -> fp16 pre-convert =================
__global__ void __launch_bounds__(256)
cvt_kernel(const float4* __restrict__ K, const float4* __restrict__ V)
{
    size_t i = (size_t)blockIdx.x * 256 + threadIdx.x;   // over 2,097,152 float4
    float4 k = K[i], v = V[i];
    reinterpret_cast<uint2*>(g_Khf)[i] = make_uint2(packh2(k.x, k.y), packh2(k.z, k.w));
    reinterpret_cast<uint2*>(g_Vhf)[i] = make_uint2(packh2(v.x, v.y), packh2(v.z, v.w));
}

// smem layout (bytes): mask 16K | K0 16K | K1 16K | V0 16K | V1 16K | stage 16K (2K/warp)
constexpr int SM_MK = 0, SM_K0 = 16384, SM_K1 = 32768, SM_V0 = 49152, SM_V1 = 65536, SM_PS = 81920;
constexpr int SMEM_BYTES = 98304;

__global__ void __launch_bounds__(256, 2)
sdpa_fused(const float* __restrict__ Q, const uint8_t* __restrict__ M,
           float* __restrict__ P, float* __restrict__ O)
{
    extern __shared__ char sm[];
    const uint32_t sb = smem_u32(sm);
    uint32_t* smMask = (uint32_t*)(sm + SM_MK);
    const int tid = threadIdx.x, wid = tid >> 5, lane = tid & 31;
    const int bh = blockIdx.y, q0 = blockIdx.x * 128;

    int pred = (tid < 128) ? (M[4 * tid + 1] != 0) : 0;
    const bool mask1B = (__syncthreads_or(pred) != 0);

    const uint8_t* M8  = M + ((size_t)bh * S + q0) * (size_t)S;
    const int*     M32 = (const int*)M + ((size_t)bh * S + q0) * (size_t)S;

    // ---- pack mask into smem bits ----
    for (int w = tid; w < 4096; w += 256) {
        int row = w >> 5, g = w & 31;
        uint32_t bits = 0;
        if (mask1B) {
            const uint8_t* p = M8 + (size_t)row * S + g * 32;
            uint4 a = *(const uint4*)p;
            uint4 b = *(const uint4*)(p + 16);
            uint32_t ww[8] = {a.x, a.y, a.z, a.w, b.x, b.y, b.z, b.w};
            #pragma unroll
            for (int j = 0; j < 8; j++) {
                uint32_t nib = ((__vcmpne4(ww[j], 0u) & 0x01010101u) * 0x01020408u) >> 24;
                bits |= nib << (j * 4);
            }
        } else {
            const int4* p = (const int4*)(M32 + (size_t)row * S + g * 32);
            #pragma unroll
            for (int j = 0; j < 8; j++) {
                int4 v = p[j];
                bits |= (uint32_t)(v.x != 0) << (j * 4);
                bits |= (uint32_t)(v.y != 0) << (j * 4 + 1);
                bits |= (uint32_t)(v.z != 0) << (j * 4 + 2);
                bits |= (uint32_t)(v.w != 0) << (j * 4 + 3);
            }
        }
        smMask[w] = bits;
    }

    // ---- Q -> split fp16 (hi into K0, lo into V0; consumed before tile loads) ----
    const float4* Qg4 = (const float4*)(Q + ((size_t)bh * S + q0) * D);
    #pragma unroll
    for (int i = 0; i < 8; i++) {
        int idx = tid + i * 256;
        int r = idx >> 4, c4 = idx & 15;
        float4 v = Qg4[idx];
        v.x *= 0.125f; v.y *= 0.125f; v.z *= 0.125f; v.w *= 0.125f;
        st_split4h(sm + SM_K0, sm + SM_V0, (uint32_t)(r * 128 + c4 * 8), v);
    }
    __syncthreads();

    uint32_t ah[4][4], al[4][4];
    {
        int j = lane >> 3, ii = lane & 7;
        int row = wid * 16 + ((j & 1) << 3) + ii;
        #pragma unroll
        for (int ks = 0; ks < 4; ks++) {
            uint32_t off = SWZ((uint32_t)(row * 128 + ((j >> 1) << 4) + ks * 32));
            ldsm_x4(ah[ks], sb + SM_K0 + off);
            ldsm_x4(al[ks], sb + SM_V0 + off);
        }
    }
    __syncthreads();   // frags hoisted; K0/V0 reusable as tile buffers

    const char* Khf = (const char*)(g_Khf + (size_t)bh * S * D);
    const char* Vhf = (const char*)(g_Vhf + (size_t)bh * S * D);

    const int r0 = wid * 16 + (lane >> 2);
    const int r1 = r0 + 8;
    const int sh2 = 2 * (lane & 3);

    const uint32_t bQrow = (uint32_t)(lane & 7);
    const uint32_t bQcol = (uint32_t)(((lane >> 3) & 1) * 16 + (lane >> 4) * 32);
    const uint32_t bVrow = (uint32_t)(((lane >> 3) & 1) * 8 + (lane & 7));
    const uint32_t bVcol = (uint32_t)((lane >> 4) * 16);

    uint32_t qkOff[2];
    {
        uint32_t xr = bQrow << 4;
        qkOff[0] = bQrow * 128 + ((bQcol)      ^ xr);
        qkOff[1] = bQrow * 128 + ((bQcol + 64) ^ xr);
    }
    uint32_t pvOff[4];
    {
        uint32_t xr = (bVrow & 7u) << 4;
        #pragma unroll
        for (int nt2 = 0; nt2 < 4; nt2++)
            pvOff[nt2] = bVrow * 128 + (((uint32_t)(nt2 * 32) + bVcol) ^ xr);
    }
    // per-warp private staging (2 KB per warp)
    const uint32_t wstage   = (uint32_t)(SM_PS + wid * 2048);
    const uint32_t stLocal0 = (uint32_t)((lane >> 2) * 128);
    const uint32_t stLocal1 = stLocal0 + 8 * 128;
    const uint32_t stXor    = ((uint32_t)(lane >> 2)) << 4;   // (r0&7)<<4 == (r1&7)<<4

    // tile loader: 16 KB tile = 128 rows x 8 chunks of 16B = 1024 chunks, 4 per thread
    auto loadTile = [&](int bufOff, const char* base) {
        #pragma unroll
        for (int i = 0; i < 4; i++) {
            int idx = tid + i * 256;                 // 0..1023
            uint32_t boff = (uint32_t)((idx >> 3) * 128 + (idx & 7) * 16);
            cp16(sb + bufOff + SWZ(boff), base + boff);
        }
    };

    // ================= Pass 1: stats (fp16 hi-only scores) =================
    float rmax0 = -3.4e38f, rmax1 = -3.4e38f, rsum0 = 0.f, rsum1 = 0.f;

    loadTile(SM_K0, Khf);
    cp_commit();

    for (int c = 0; c < 8; c++) {
        if (c < 7) { loadTile((c & 1) ? SM_K0 : SM_K1, Khf + (size_t)(c + 1) * 16384); cp_commit(); cp_wait<1>(); }
        else       { cp_wait<0>(); }
        __syncthreads();
        const uint32_t kb = sb + ((c & 1) ? SM_K1 : SM_K0);

        #pragma unroll
        for (int g = 0; g < 2; g++) {
            float cf[8][4];
            #pragma unroll
            for (int n8 = 0; n8 < 8; n8++) {
                cf[n8][0] = cf[n8][1] = cf[n8][2] = cf[n8][3] = 0.f;
                int nt = g * 8 + n8;
                #pragma unroll
                for (int ks2 = 0; ks2 < 2; ks2++) {
                    uint32_t off = (uint32_t)(nt * 1024) + qkOff[ks2];
                    uint32_t bh4[4];
                    ldsm_x4(bh4, kb + off);
                    mma_f16(cf[n8], ah[2*ks2],   bh4);
                    mma_f16(cf[n8], ah[2*ks2+1], bh4 + 2);
                }
            }
            uint32_t w0a = smMask[r0 * 32 + c * 4 + g * 2];
            uint32_t w0b = smMask[r0 * 32 + c * 4 + g * 2 + 1];
            uint32_t w1a = smMask[r1 * 32 + c * 4 + g * 2];
            uint32_t w1b = smMask[r1 * 32 + c * 4 + g * 2 + 1];
            float gm0 = -3.4e38f, gm1 = -3.4e38f;
            #pragma unroll
            for (int n8 = 0; n8 < 8; n8++) {
                uint32_t m0 = ((n8 < 4 ? w0a : w0b) >> ((n8 & 3) * 8 + sh2)) & 3u;
                uint32_t m1 = ((n8 < 4 ? w1a : w1b) >> ((n8 & 3) * 8 + sh2)) & 3u;
                cf[n8][0] = (m0 & 1u) ? -1e9f : cf[n8][0];
                cf[n8][1] = (m0 & 2u) ? -1e9f : cf[n8][1];
                cf[n8][2] = (m1 & 1u) ? -1e9f : cf[n8][2];
                cf[n8][3] = (m1 & 2u) ? -1e9f : cf[n8][3];
                gm0 = fmaxf(gm0, fmaxf(cf[n8][0], cf[n8][1]));
                gm1 = fmaxf(gm1, fmaxf(cf[n8][2], cf[n8][3]));
            }
            float nm0 = fmaxf(rmax0, gm0), nm1 = fmaxf(rmax1, gm1);
            float s0 = 0.f, s1 = 0.f;
            #pragma unroll
            for (int n8 = 0; n8 < 8; n8++) {
                s0 += __expf(cf[n8][0] - nm0) + __expf(cf[n8][1] - nm0);
                s1 += __expf(cf[n8][2] - nm1) + __expf(cf[n8][3] - nm1);
            }
            rsum0 = rsum0 * __expf(rmax0 - nm0) + s0; rmax0 = nm0;
            rsum1 = rsum1 * __expf(rmax1 - nm1) + s1; rmax1 = nm1;
        }
        __syncthreads();
    }

    // quad reduce (lanes sharing a row)
    #pragma unroll
    for (int o = 1; o <= 2; o <<= 1) {
        float om = __shfl_xor_sync(0xffffffffu, rmax0, o);
        float os = __shfl_xor_sync(0xffffffffu, rsum0, o);
        float nm = fmaxf(rmax0, om);
        rsum0 = rsum0 * __expf(rmax0 - nm) + os * __expf(om - nm); rmax0 = nm;
        om = __shfl_xor_sync(0xffffffffu, rmax1, o);
        os = __shfl_xor_sync(0xffffffffu, rsum1, o);
        nm = fmaxf(rmax1, om);
        rsum1 = rsum1 * __expf(rmax1 - nm) + os * __expf(om - nm); rmax1 = nm;
    }
    const float mx0 = rmax0, iv0 = 1.0f / rsum0;
    const float mx1 = rmax1, iv1 = 1.0f / rsum1;

    // ================= Pass 2: probs + PV (no per-batch block barriers) =================
    float co[8][4];
    #pragma unroll
    for (int n = 0; n < 8; n++) co[n][0] = co[n][1] = co[n][2] = co[n][3] = 0.f;

    float* Ag = P + ((size_t)bh * S + q0) * (size_t)S;

    loadTile(SM_K0, Khf);
    loadTile(SM_V0, Vhf);
    cp_commit();

    for (int t = 0; t < 8; t++) {
        if (t < 7) {
            loadTile((t & 1) ? SM_K0 : SM_K1, Khf + (size_t)(t + 1) * 16384);
            loadTile((t & 1) ? SM_V0 : SM_V1, Vhf + (size_t)(t + 1) * 16384);
            cp_commit();
            cp_wait<1>();
        } else {
            cp_wait<0>();
        }
        __syncthreads();
        const uint32_t kb = sb + ((t & 1) ? SM_K1 : SM_K0);
        const uint32_t vb = sb + ((t & 1) ? SM_V1 : SM_V0);

        #pragma unroll
        for (int g2 = 0; g2 < 4; g2++) {          // 32-key batches
            float cf[4][4];
            #pragma unroll
            for (int n8 = 0; n8 < 4; n8++) {
                cf[n8][0] = cf[n8][1] = cf[n8][2] = cf[n8][3] = 0.f;
                int nt = g2 * 4 + n8;
                #pragma unroll
                for (int ks2 = 0; ks2 < 2; ks2++) {
                    uint32_t off = (uint32_t)(nt * 1024) + qkOff[ks2];
                    uint32_t bh4[4];
                    ldsm_x4(bh4, kb + off);
                    mma_f16(cf[n8], ah[2*ks2],   bh4);
                    mma_f16(cf[n8], al[2*ks2],   bh4);
                    mma_f16(cf[n8], ah[2*ks2+1], bh4 + 2);
                    mma_f16(cf[n8], al[2*ks2+1], bh4 + 2);
                }
            }
            uint32_t w0 = smMask[r0 * 32 + t * 4 + g2];
            uint32_t w1 = smMask[r1 * 32 + t * 4 + g2];
            uint32_t ph[2][4], pl[2][4];
            __syncwarp();                           // staging free (prior readback done)
            #pragma unroll
            for (int n8 = 0; n8 < 4; n8++) {
                uint32_t stC = ((uint32_t)(n8 * 32 + sh2 * 4)) ^ stXor;
                uint32_t m0 = (w0 >> (n8 * 8 + sh2)) & 3u;
                uint32_t m1 = (w1 >> (n8 * 8 + sh2)) & 3u;
                float p0 = (m0 & 1u) ? 0.f : __expf(cf[n8][0] - mx0) * iv0;
                float p1 = (m0 & 2u) ? 0.f : __expf(cf[n8][1] - mx0) * iv0;
                float p2 = (m1 & 1u) ? 0.f : __expf(cf[n8][2] - mx1) * iv1;
                float p3 = (m1 & 2u) ? 0.f : __expf(cf[n8][3] - mx1) * iv1;
                *(float2*)(sm + wstage + stLocal0 + stC) = make_float2(p0, p1);
                *(float2*)(sm + wstage + stLocal1 + stC) = make_float2(p2, p3);
                uint32_t h01 = packh2(p0, p1), h23 = packh2(p2, p3);
                float2 f01 = unpackh2(h01), f23 = unpackh2(h23);
                uint32_t l01 = packh2(p0 - f01.x, p1 - f01.y);
                uint32_t l23 = packh2(p2 - f23.x, p3 - f23.y);
                int ks2 = n8 >> 1, hi2 = (n8 & 1) << 1;
                ph[ks2][hi2] = h01; ph[ks2][hi2 + 1] = h23;
                pl[ks2][hi2] = l01; pl[ks2][hi2 + 1] = l23;
            }
            __syncwarp();                           // staging writes visible warp-wide
            // per-warp coalesced prob writeback: own 16 rows x 32 cols
            #pragma unroll
            for (int i = 0; i < 4; i++) {
                int rowL = i * 4 + (lane >> 3);
                int c4 = lane & 7;
                uint32_t a = wstage + (uint32_t)(rowL * 128)
                           + (((uint32_t)(c4 * 16)) ^ (((uint32_t)(rowL & 7)) << 4));
                float4 pv = *(const float4*)(sm + a);
                *(float4*)(Ag + (size_t)(wid * 16 + rowL) * S + t * 128 + g2 * 32 + c4 * 4) = pv;
            }
            // PV accumulate (V single fp16, P split in registers)
            #pragma unroll
            for (int ks2 = 0; ks2 < 2; ks2++) {
                #pragma unroll
                for (int nt2 = 0; nt2 < 4; nt2++) {
                    uint32_t off = (uint32_t)((g2 * 32 + ks2 * 16) * 128) + pvOff[nt2];
                    uint32_t bh4[4];
                    ldsm_x4t(bh4, vb + off);
                    mma_f16(co[2*nt2],   ph[ks2], bh4);
                    mma_f16(co[2*nt2],   pl[ks2], bh4);
                    mma_f16(co[2*nt2+1], ph[ks2], bh4 + 2);
                    mma_f16(co[2*nt2+1], pl[ks2], bh4 + 2);
                }
            }
        }
        __syncthreads();   // all warps done with buffers before next chunk's loads
    }

    // ---- write context ----
    float* Og = O + ((size_t)bh * S + q0) * D;
    #pragma unroll
    for (int nt = 0; nt < 8; nt++) {
        int col = nt * 8 + sh2;
        *(float2*)(Og + (size_t)r0 * D + col) = make_float2(co[nt][0], co[nt][1]);
        *(float2*)(Og + (size_t)r1 * D + col) = make_float2(co[nt][2], co[nt][3]);
    }
}

} // namespace

extern "C" void kernel_launch(void* const* d_in, const int* in_sizes, int n_in,
                              void* d_out, int out_size) {
    const float*   Q = (const float*)d_in[0];
    const float*   K = (const float*)d_in[1];
    const float*   V = (const float*)d_in[2];
    const uint8_t* M = (const uint8_t*)d_in[3];

    const long long NCTX = 8LL * 16 * 1024 * 64;
    const long long NATT = 8LL * 16 * 1024 * 1024;

    float* ctx  = nullptr;
    float* attn = nullptr;
    if ((long long)out_size >= NCTX + NATT) {
        ctx  = (float*)d_out;
        attn = (float*)d_out + NCTX;
    } else if ((long long)out_size == NATT) {
        attn = (float*)d_out;
    } else {
        ctx = (float*)d_out;
    }
    if (!attn || !ctx) return;

    cudaFuncSetAttribute((const void*)sdpa_fused,
                         cudaFuncAttributeMaxDynamicSharedMemorySize, SMEM_BYTES);

    cvt_kernel<<<8192, 256>>>((const float4*)K, (const float4*)V);

    dim3 grid(8, BH);
    sdpa_fused<<<grid, 256, SMEM_BYTES>>>(Q, M, attn, ctx);
}